// round 8
// baseline (speedup 1.0000x reference)
#include <cuda_runtime.h>
#include <cuda_bf16.h>
#include <cstdint>

#define BB 64
#define SS 512
#define HH 768
#define LL 9

#define RB 128          // rows per block (gemm)
#define KC 32           // k per chunk
#define NCHUNK (HH / KC)        // 24
#define ASTRIDE 36      // A smem row stride (u32) -> conflict-free frag LDS
#define ASM_U32 (RB * ASTRIDE)          // 4608
#define BFR_U32 (96 * 2 * 64)           // 12288: [kstep][ntile][lane*2+half]
#define GEMM_SMEM_BYTES ((ASM_U32 + BFR_U32) * 4)   // 67584

__device__ float g_feats[(size_t)BB * SS * LL];
__device__ float g_part[BB];

__device__ __forceinline__ float ex2f_(float x) {
    float y; asm("ex2.approx.ftz.f32 %0, %1;" : "=f"(y) : "f"(x)); return y;
}
__device__ __forceinline__ float lg2f_(float x) {
    float y; asm("lg2.approx.f32 %0, %1;" : "=f"(y) : "f"(x)); return y;
}
__device__ __forceinline__ uint32_t f2tf32_(float v) {
    uint32_t t; asm("cvt.rna.tf32.f32 %0, %1;" : "=r"(t) : "f"(v)); return t;
}

// ---------------------------------------------------------------------------
// Kernel 1 (tensor): feats[m][l] = hidden[m][:].W[l][:] + b[l]
// tf32 mma.sync.m16n8k8, N padded 9->16 (2 n-tiles), K chunked by 32.
// Block 256 thr = 8 warps, 128 rows; warp w owns rows w*16..w*16+15.
// A: staged per chunk into smem (tf32, stride 36 -> conflict-free LDS),
//    register prefetch of chunk k+1 overlaps compute.
// B: fragment-ordered tf32 table in smem built once per block ->
//    mainloop B loads are conflict-free LDS.64.
// smem 67.6KB dynamic -> 3 blocks/SM; grid 256 = 1 wave.
// ---------------------------------------------------------------------------
__global__ __launch_bounds__(256)
void gemm_kernel(const float* __restrict__ hidden,
                 const float* __restrict__ W,
                 const float* __restrict__ bias,
                 float* __restrict__ feats) {
    extern __shared__ uint32_t dynsm[];
    uint32_t* Asm = dynsm;             // [RB][ASTRIDE]
    uint32_t* Bfr = dynsm + ASM_U32;   // [96][2][64]

    const int tid  = threadIdx.x;
    const int warp = tid >> 5;
    const int lane = tid & 31;
    const int g = lane >> 2;           // 0..7
    const int c = lane & 3;            // 0..3

    // ---- build B fragment table (once per block) ----
    for (int i = tid; i < BFR_U32; i += 256) {
        int half = i & 1;
        int ln   = (i >> 1) & 31;
        int nt   = (i >> 6) & 1;
        int s    = i >> 7;             // global k-step 0..95
        int n = nt * 8 + (ln >> 2);
        int k = s * 8 + (ln & 3) + half * 4;
        float v = (n < LL) ? __ldg(&W[n * HH + k]) : 0.f;
        Bfr[i] = f2tf32_(v);
    }

    const int rowbase = blockIdx.x * RB;

    // ---- prefetch chunk 0 ----
    float4 pf[4];
#pragma unroll
    for (int i = 0; i < 4; ++i) {
        int idx = tid + 256 * i;       // 0..1023
        int r = idx >> 3, c4 = idx & 7;
        pf[i] = *reinterpret_cast<const float4*>(
            hidden + (size_t)(rowbase + r) * HH + c4 * 4);
    }

    float acc[2][4];
#pragma unroll
    for (int nt = 0; nt < 2; ++nt)
#pragma unroll
        for (int j = 0; j < 4; ++j) acc[nt][j] = 0.f;

    __syncthreads();   // Bfr table ready

#pragma unroll 1
    for (int kc = 0; kc < NCHUNK; ++kc) {
        // stage prefetched chunk as tf32
#pragma unroll
        for (int i = 0; i < 4; ++i) {
            int idx = tid + 256 * i;
            int r = idx >> 3, c4 = idx & 7;
            uint4 t;
            t.x = f2tf32_(pf[i].x); t.y = f2tf32_(pf[i].y);
            t.z = f2tf32_(pf[i].z); t.w = f2tf32_(pf[i].w);
            reinterpret_cast<uint4*>(Asm + r * ASTRIDE)[c4] = t;
        }
        __syncthreads();   // Asm ready

        if (kc < NCHUNK - 1) {
#pragma unroll
            for (int i = 0; i < 4; ++i) {
                int idx = tid + 256 * i;
                int r = idx >> 3, c4 = idx & 7;
                pf[i] = *reinterpret_cast<const float4*>(
                    hidden + (size_t)(rowbase + r) * HH + (kc + 1) * KC + c4 * 4);
            }
        }

        // compute: 4 k-steps x 2 n-tiles of m16n8k8
#pragma unroll
        for (int s = 0; s < 4; ++s) {
            const uint32_t* a0p = Asm + (warp * 16 + g) * ASTRIDE + s * 8 + c;
            uint32_t a0 = a0p[0];
            uint32_t a2 = a0p[4];
            uint32_t a1 = a0p[8 * ASTRIDE];
            uint32_t a3 = a0p[8 * ASTRIDE + 4];
            int sg = kc * 4 + s;
#pragma unroll
            for (int nt = 0; nt < 2; ++nt) {
                uint2 b = *reinterpret_cast<const uint2*>(
                    Bfr + sg * 128 + nt * 64 + lane * 2);
                asm volatile(
                    "mma.sync.aligned.m16n8k8.row.col.f32.tf32.tf32.f32 "
                    "{%0,%1,%2,%3}, {%4,%5,%6,%7}, {%8,%9}, {%0,%1,%2,%3};"
                    : "+f"(acc[nt][0]), "+f"(acc[nt][1]),
                      "+f"(acc[nt][2]), "+f"(acc[nt][3])
                    : "r"(a0), "r"(a1), "r"(a2), "r"(a3),
                      "r"(b.x), "r"(b.y));
            }
        }
        __syncthreads();   // compute done before next overwrite
    }

    // ---- epilogue: D frag (row g / g+8, cols 2c,2c+1 per ntile) ----
    const int row0 = rowbase + warp * 16 + g;
    const int row1 = row0 + 8;
#pragma unroll
    for (int nt = 0; nt < 2; ++nt) {
        int col0 = nt * 8 + 2 * c;
        int col1 = col0 + 1;
        if (col0 < LL) {
            float b0 = __ldg(&bias[col0]);
            feats[(size_t)row0 * LL + col0] = acc[nt][0] + b0;
            feats[(size_t)row1 * LL + col0] = acc[nt][2] + b0;
        }
        if (col1 < LL) {
            float b1 = __ldg(&bias[col1]);
            feats[(size_t)row0 * LL + col1] = acc[nt][1] + b1;
            feats[(size_t)row1 * LL + col1] = acc[nt][3] + b1;
        }
    }
}

// ---------------------------------------------------------------------------
// Kernel 2: one block (256 thr, 8 warps) per batch.  (unchanged from R6)
// Blocked parallel CRF scan: warp s computes the 9x9 linear-domain transfer
// matrix product over steps t in [max(1,64s), min(len,64(s+1))):
//     M <- M * S_t,  S_t[i][j] = E[i][j] * exp(f_t[j])
// 27 lanes own 3 matrix entries each. Exact power-of-2 rescale every 8 steps.
// Warp 0 then chains alpha0 through the 8 matrices.
// ---------------------------------------------------------------------------
__global__ __launch_bounds__(256, 1)
void crf_kernel(const float* __restrict__ feats,
                const float* __restrict__ start_tr,
                const float* __restrict__ end_tr,
                const float* __restrict__ trans,
                const int* __restrict__ labels,
                const unsigned char* __restrict__ mask8,
                float* __restrict__ partials) {
    __shared__ float sm_ef[SS * LL];       // 18432 B: exp(feats)
    __shared__ float sm_M[8][81];
    __shared__ float sm_C[8];
    __shared__ float sm_red[8];
    __shared__ float sm_score;
    __shared__ int   sm_len;

    const int b = blockIdx.x;
    const int tid = threadIdx.x;
    const int wid = tid >> 5;
    const int lane = tid & 31;
    const unsigned FULL = 0xffffffffu;
    const float LOG2E = 1.4426950408889634f;
    const float LN2   = 0.6931471805599453f;

    // ---- sequence length (mask monotone: mask[t] = t < len) ----
    const unsigned char* mrow = mask8 + (size_t)b * SS;
    int cnt = 0;
    for (int t = tid; t < SS; t += 256) cnt += (int)mrow[t];
    cnt = __reduce_add_sync(FULL, cnt);
    if (lane == 0) sm_red[wid] = (float)cnt;
    __syncthreads();
    if (tid == 0) {
        int l = 0;
        for (int w = 0; w < 8; w++) l += (int)sm_red[w];
        sm_len = l;
    }
    __syncthreads();
    int len = sm_len;
    if (len < SS / 2) {   // fallback: mask stored as int32 (lens >= 256 if u8)
        const int* mi = reinterpret_cast<const int*>(mask8) + (size_t)b * SS;
        cnt = 0;
        for (int t = tid; t < SS; t += 256) cnt += (mi[t] != 0);
        cnt = __reduce_add_sync(FULL, cnt);
        if (lane == 0) sm_red[wid] = (float)cnt;
        __syncthreads();
        if (tid == 0) {
            int l = 0;
            for (int w = 0; w < 8; w++) l += (int)sm_red[w];
            sm_len = l;
        }
        __syncthreads();
        len = sm_len;
    }
    __syncthreads();

    // ---- ef table: sm_ef[t*9+j] = exp(feats[b][t][j]) (vectorized) ----
    const float* frow = feats + (size_t)b * SS * LL;
    for (int i = tid; i < (SS * LL) / 4; i += 256) {
        float4 v = reinterpret_cast<const float4*>(frow)[i];
        float4 e;
        e.x = ex2f_(v.x * LOG2E); e.y = ex2f_(v.y * LOG2E);
        e.z = ex2f_(v.z * LOG2E); e.w = ex2f_(v.w * LOG2E);
        reinterpret_cast<float4*>(sm_ef)[i] = e;
    }

    // ---- gold path score (block-parallel over t) ----
    const int* lab = labels + (size_t)b * SS;
    float sc = 0.f;
    for (int t = tid; t < SS; t += 256) {
        int lt = lab[t];
        if (t == 0) {
            sc += __ldg(&start_tr[lt]) + frow[lt];
        } else if (t < len) {
            sc += __ldg(&trans[lab[t - 1] * LL + lt]) + frow[t * LL + lt];
        }
        if (t == len - 1) sc += __ldg(&end_tr[lt]);
    }
#pragma unroll
    for (int o = 16; o > 0; o >>= 1) sc += __shfl_xor_sync(FULL, sc, o);
    if (lane == 0) sm_red[wid] = sc;
    __syncthreads();
    if (tid == 0) {
        float s = 0.f;
        for (int w = 0; w < 8; w++) s += sm_red[w];
        sm_score = s;
    }

    // ---- per-warp segment matrix product ----
    const int a = (lane < 27) ? (lane / 3) : 8;   // owned row
    const int g = lane % 3;                       // owned col-triple
    float Ec[LL][3];                              // E[i][3g+k]
#pragma unroll
    for (int i = 0; i < LL; i++)
#pragma unroll
        for (int k = 0; k < 3; k++)
            Ec[i][k] = __expf(__ldg(&trans[i * LL + 3 * g + k]));

    float Mr[3];
#pragma unroll
    for (int k = 0; k < 3; k++) Mr[k] = (3 * g + k == a) ? 1.f : 0.f;
    float Cw = 0.f;

    __syncthreads();  // sm_ef ready

    const int t0 = max(1, wid * 64);
    const int t1 = min(len, (wid + 1) * 64);
    for (int t = t0; t < t1; ++t) {
        float ef0 = sm_ef[t * LL + 3 * g + 0];
        float ef1 = sm_ef[t * LL + 3 * g + 1];
        float ef2 = sm_ef[t * LL + 3 * g + 2];

        float m[LL];
#pragma unroll
        for (int i = 0; i < LL; i++)
            m[i] = __shfl_sync(FULL, Mr[i % 3], a * 3 + i / 3);

        float o0a = m[0] * Ec[0][0], o0b = m[1] * Ec[1][0];
        float o1a = m[0] * Ec[0][1], o1b = m[1] * Ec[1][1];
        float o2a = m[0] * Ec[0][2], o2b = m[1] * Ec[1][2];
#pragma unroll
        for (int i = 2; i < LL; i += 2) {
            o0a = fmaf(m[i], Ec[i][0], o0a);
            o1a = fmaf(m[i], Ec[i][1], o1a);
            o2a = fmaf(m[i], Ec[i][2], o2a);
            if (i + 1 < LL) {
                o0b = fmaf(m[i + 1], Ec[i + 1][0], o0b);
                o1b = fmaf(m[i + 1], Ec[i + 1][1], o1b);
                o2b = fmaf(m[i + 1], Ec[i + 1][2], o2b);
            }
        }
        Mr[0] = (o0a + o0b) * ef0;
        Mr[1] = (o1a + o1b) * ef1;
        Mr[2] = (o2a + o2b) * ef2;

        if ((t & 7) == 7) {
            float u = __shfl_sync(FULL, Mr[0], 0);
            int e = (__float_as_int(u) >> 23) & 255;
            float scale = __int_as_float((254 - e) << 23);  // 2^(127-e)
            Mr[0] *= scale; Mr[1] *= scale; Mr[2] *= scale;
            Cw += (float)(e - 127);
        }
    }
    if (lane < 27) {
#pragma unroll
        for (int k = 0; k < 3; k++) sm_M[wid][a * LL + 3 * g + k] = Mr[k];
    }
    if (lane == 0) sm_C[wid] = Cw;
    __syncthreads();

    // ---- warp 0: chain alpha through the 8 segment matrices ----
    if (wid == 0) {
        float al = (lane < LL) ? sm_ef[lane] * __expf(__ldg(&start_tr[lane])) : 0.f;
        float C = 0.f;
#pragma unroll 1
        for (int s = 0; s < 8; ++s) {
            float m[LL];
#pragma unroll
            for (int i = 0; i < LL; i++) m[i] = __shfl_sync(FULL, al, i);
            const int jj = (lane < LL) ? lane : 0;
            float sum = 0.f;
#pragma unroll
            for (int i = 0; i < LL; i++)
                sum = fmaf(m[i], sm_M[s][i * LL + jj], sum);
            al = (lane < LL) ? sum : 0.f;
            C += sm_C[s];
            float u = __shfl_sync(FULL, al, 0);
            int e = (__float_as_int(u) >> 23) & 255;
            float scale = __int_as_float((254 - e) << 23);
            al *= scale;
            C += (float)(e - 127);
        }
        float ev = (lane < LL) ? al * __expf(__ldg(&end_tr[lane])) : 0.f;
#pragma unroll
        for (int o = 16; o > 0; o >>= 1) ev += __shfl_xor_sync(FULL, ev, o);
        float logden = LN2 * (C + lg2f_(ev));
        if (lane == 0) partials[b] = logden - sm_score;
    }
}

// ---------------------------------------------------------------------------
// Kernel 3: mean over 64 per-batch NLLs
// ---------------------------------------------------------------------------
__global__ void finalize_kernel(const float* __restrict__ p, float* __restrict__ out) {
    int lane = threadIdx.x;  // 32 threads
    float v = p[lane] + p[lane + 32];
#pragma unroll
    for (int o = 16; o > 0; o >>= 1) v += __shfl_xor_sync(0xffffffffu, v, o);
    if (lane == 0) out[0] = v * (1.0f / BB);
}

// ---------------------------------------------------------------------------
extern "C" void kernel_launch(void* const* d_in, const int* in_sizes, int n_in,
                              void* d_out, int out_size) {
    const float* hidden  = (const float*)d_in[0];
    const float* W       = (const float*)d_in[1];
    const float* bias    = (const float*)d_in[2];
    const float* start_t = (const float*)d_in[3];
    const float* end_t   = (const float*)d_in[4];
    const float* trans   = (const float*)d_in[5];
    const int*   labels  = (const int*)d_in[6];
    const unsigned char* mask = (const unsigned char*)d_in[7];
    float* out = (float*)d_out;

    float* feats = nullptr;
    float* part  = nullptr;
    cudaGetSymbolAddress((void**)&feats, g_feats);
    cudaGetSymbolAddress((void**)&part,  g_part);

    static bool attr_set = false;
    if (!attr_set) {
        cudaFuncSetAttribute(gemm_kernel,
                             cudaFuncAttributeMaxDynamicSharedMemorySize,
                             GEMM_SMEM_BYTES);
        attr_set = true;
    }

    gemm_kernel<<<256, 256, GEMM_SMEM_BYTES>>>(hidden, W, bias, feats);
    crf_kernel<<<BB, 256>>>(feats, start_t, end_t, trans, labels, mask, part);
    finalize_kernel<<<1, 32>>>(part, out);
}

// round 9
// speedup vs baseline: 1.2597x; 1.2597x over previous
#include <cuda_runtime.h>
#include <cuda_bf16.h>
#include <cstdint>

#define BB 64
#define SS 512
#define HH 768
#define LL 9

#define RB 128                    // rows per block (gemm)
#define KC 32                     // k per chunk
#define NCHUNK (HH / KC)          // 24
#define ASTRIDE 36                // A smem row stride (u32) -> conflict-free
#define ASTAGE_U32 (RB * ASTRIDE) // 4608 u32 per stage
#define B0_U32 (96 * 64)          // 6144: ntile0 frag table
#define B1_U32 (96 * 8)           // 768:  ntile1 compact (only n=8 real)
#define SMEM_U32 (2 * ASTAGE_U32 + B0_U32 + B1_U32)   // 16128
#define GEMM_SMEM_BYTES (SMEM_U32 * 4)                // 64512

__device__ float g_feats[(size_t)BB * SS * LL];
__device__ float g_part[BB];

__device__ __forceinline__ float ex2f_(float x) {
    float y; asm("ex2.approx.ftz.f32 %0, %1;" : "=f"(y) : "f"(x)); return y;
}
__device__ __forceinline__ float lg2f_(float x) {
    float y; asm("lg2.approx.f32 %0, %1;" : "=f"(y) : "f"(x)); return y;
}
__device__ __forceinline__ uint32_t f2tf32_(float v) {
    uint32_t t; asm("cvt.rna.tf32.f32 %0, %1;" : "=r"(t) : "f"(v)); return t;
}
__device__ __forceinline__ void cpasync16_(uint32_t dst, const void* src) {
    asm volatile("cp.async.cg.shared.global [%0], [%1], 16;"
                 :: "r"(dst), "l"(src));
}

// ---------------------------------------------------------------------------
// Kernel 1 (tensor): feats[m][l] = hidden[m][:].W[l][:] + b[l]
// tf32 mma.sync.m16n8k8; A staged RAW (fp32 bits; tf32 HW reads upper 19
// bits -> truncation, well within tolerance) via 2-stage cp.async.cg
// pipeline -> zero per-chunk register traffic. B: fragment-ordered table
// (rna-converted once per block); ntile1 stored compact (only n=8 real).
// smem 64.5KB -> 3 blocks/SM. Block 256 thr = 8 warps x 16 rows.
// ---------------------------------------------------------------------------
__global__ __launch_bounds__(256)
void gemm_kernel(const float* __restrict__ hidden,
                 const float* __restrict__ W,
                 const float* __restrict__ bias,
                 float* __restrict__ feats) {
    extern __shared__ uint32_t dynsm[];
    uint32_t* Abuf = dynsm;                      // [2][RB][ASTRIDE]
    uint32_t* Bfr0 = dynsm + 2 * ASTAGE_U32;     // [96][64]
    uint32_t* Bfr1 = Bfr0 + B0_U32;              // [96][8]
    const uint32_t sbase =
        static_cast<uint32_t>(__cvta_generic_to_shared(dynsm));

    const int tid  = threadIdx.x;
    const int warp = tid >> 5;
    const int lane = tid & 31;
    const int g = lane >> 2;           // 0..7
    const int c = lane & 3;            // 0..3

    // ---- build B fragment tables (once per block) ----
    // ntile0: n = ln>>2 (0..7), k = s*8 + (ln&3) + half*4
    for (int i = tid; i < B0_U32; i += 256) {
        int half = i & 1;
        int ln   = (i >> 1) & 31;
        int s    = i >> 6;
        int n = ln >> 2;
        int k = s * 8 + (ln & 3) + half * 4;
        Bfr0[i] = f2tf32_(__ldg(&W[n * HH + k]));
    }
    // ntile1 compact: lanes 0..3 (g=0 -> n=8), 2 values each
    for (int i = tid; i < B1_U32; i += 256) {
        int half = i & 1;
        int ln   = (i >> 1) & 3;
        int s    = i >> 3;
        int k = s * 8 + ln + half * 4;
        Bfr1[i] = f2tf32_(__ldg(&W[8 * HH + k]));
    }

    const int rowbase = blockIdx.x * RB;

    // ---- staging lambda: chunk kc -> stage buffer st ----
    auto stage = [&](int st, int kc) {
#pragma unroll
        for (int i = 0; i < 4; ++i) {
            int idx = tid + 256 * i;           // 0..1023
            int r = idx >> 3, c4 = idx & 7;
            uint32_t dst = sbase +
                (uint32_t)(st * ASTAGE_U32 + r * ASTRIDE + c4 * 4) * 4u;
            const float* src = hidden + (size_t)(rowbase + r) * HH
                               + kc * KC + c4 * 4;
            cpasync16_(dst, src);
        }
        asm volatile("cp.async.commit_group;");
    };

    float acc[2][4];
#pragma unroll
    for (int nt = 0; nt < 2; ++nt)
#pragma unroll
        for (int j = 0; j < 4; ++j) acc[nt][j] = 0.f;

    // prologue: stages 0 and 1 in flight
    stage(0, 0);
    stage(1, 1);
    __syncthreads();   // B tables ready (also covers first-stage visibility pattern)

#pragma unroll 1
    for (int kc = 0; kc < NCHUNK; ++kc) {
        if (kc + 1 < NCHUNK)
            asm volatile("cp.async.wait_group 1;");
        else
            asm volatile("cp.async.wait_group 0;");
        __syncthreads();   // staged chunk visible to all warps

        const uint32_t* As = Abuf + (kc & 1) * ASTAGE_U32;
#pragma unroll
        for (int s = 0; s < 4; ++s) {
            const uint32_t* a0p = As + (warp * 16 + g) * ASTRIDE + s * 8 + c;
            uint32_t a0 = a0p[0];
            uint32_t a2 = a0p[4];
            uint32_t a1 = a0p[8 * ASTRIDE];
            uint32_t a3 = a0p[8 * ASTRIDE + 4];
            int sg = kc * 4 + s;

            uint2 b0 = *reinterpret_cast<const uint2*>(Bfr0 + sg * 64 + lane * 2);
            asm volatile(
                "mma.sync.aligned.m16n8k8.row.col.f32.tf32.tf32.f32 "
                "{%0,%1,%2,%3}, {%4,%5,%6,%7}, {%8,%9}, {%0,%1,%2,%3};"
                : "+f"(acc[0][0]), "+f"(acc[0][1]),
                  "+f"(acc[0][2]), "+f"(acc[0][3])
                : "r"(a0), "r"(a1), "r"(a2), "r"(a3),
                  "r"(b0.x), "r"(b0.y));

            uint2 b1 = make_uint2(0u, 0u);
            if (lane < 4)
                b1 = *reinterpret_cast<const uint2*>(Bfr1 + sg * 8 + lane * 2);
            asm volatile(
                "mma.sync.aligned.m16n8k8.row.col.f32.tf32.tf32.f32 "
                "{%0,%1,%2,%3}, {%4,%5,%6,%7}, {%8,%9}, {%0,%1,%2,%3};"
                : "+f"(acc[1][0]), "+f"(acc[1][1]),
                  "+f"(acc[1][2]), "+f"(acc[1][3])
                : "r"(a0), "r"(a1), "r"(a2), "r"(a3),
                  "r"(b1.x), "r"(b1.y));
        }
        __syncthreads();   // all warps done with this buffer
        if (kc + 2 < NCHUNK) stage(kc & 1, kc + 2);
    }

    // ---- epilogue: D frag (rows g/g+8, cols 2c,2c+1 per ntile) ----
    const int row0 = rowbase + warp * 16 + g;
    const int row1 = row0 + 8;
#pragma unroll
    for (int nt = 0; nt < 2; ++nt) {
        int col0 = nt * 8 + 2 * c;
        int col1 = col0 + 1;
        if (col0 < LL) {
            float b0 = __ldg(&bias[col0]);
            feats[(size_t)row0 * LL + col0] = acc[nt][0] + b0;
            feats[(size_t)row1 * LL + col0] = acc[nt][2] + b0;
        }
        if (col1 < LL) {
            float b1 = __ldg(&bias[col1]);
            feats[(size_t)row0 * LL + col1] = acc[nt][1] + b1;
            feats[(size_t)row1 * LL + col1] = acc[nt][3] + b1;
        }
    }
}

// ---------------------------------------------------------------------------
// Kernel 2: one block (256 thr, 8 warps) per batch.  (unchanged, proven)
// Blocked parallel CRF scan: warp s computes the 9x9 linear-domain transfer
// matrix product over its 64-step segment; warp 0 chains alpha through the
// 8 matrices. Exact power-of-2 rescale every 8 steps.
// ---------------------------------------------------------------------------
__global__ __launch_bounds__(256, 1)
void crf_kernel(const float* __restrict__ feats,
                const float* __restrict__ start_tr,
                const float* __restrict__ end_tr,
                const float* __restrict__ trans,
                const int* __restrict__ labels,
                const unsigned char* __restrict__ mask8,
                float* __restrict__ partials) {
    __shared__ float sm_ef[SS * LL];
    __shared__ float sm_M[8][81];
    __shared__ float sm_C[8];
    __shared__ float sm_red[8];
    __shared__ float sm_score;
    __shared__ int   sm_len;

    const int b = blockIdx.x;
    const int tid = threadIdx.x;
    const int wid = tid >> 5;
    const int lane = tid & 31;
    const unsigned FULL = 0xffffffffu;
    const float LOG2E = 1.4426950408889634f;
    const float LN2   = 0.6931471805599453f;

    // ---- sequence length (mask monotone: mask[t] = t < len) ----
    const unsigned char* mrow = mask8 + (size_t)b * SS;
    int cnt = 0;
    for (int t = tid; t < SS; t += 256) cnt += (int)mrow[t];
    cnt = __reduce_add_sync(FULL, cnt);
    if (lane == 0) sm_red[wid] = (float)cnt;
    __syncthreads();
    if (tid == 0) {
        int l = 0;
        for (int w = 0; w < 8; w++) l += (int)sm_red[w];
        sm_len = l;
    }
    __syncthreads();
    int len = sm_len;
    if (len < SS / 2) {   // fallback: mask stored as int32 (lens >= 256 if u8)
        const int* mi = reinterpret_cast<const int*>(mask8) + (size_t)b * SS;
        cnt = 0;
        for (int t = tid; t < SS; t += 256) cnt += (mi[t] != 0);
        cnt = __reduce_add_sync(FULL, cnt);
        if (lane == 0) sm_red[wid] = (float)cnt;
        __syncthreads();
        if (tid == 0) {
            int l = 0;
            for (int w = 0; w < 8; w++) l += (int)sm_red[w];
            sm_len = l;
        }
        __syncthreads();
        len = sm_len;
    }
    __syncthreads();

    // ---- ef table: sm_ef[t*9+j] = exp(feats[b][t][j]) (vectorized) ----
    const float* frow = feats + (size_t)b * SS * LL;
    for (int i = tid; i < (SS * LL) / 4; i += 256) {
        float4 v = reinterpret_cast<const float4*>(frow)[i];
        float4 e;
        e.x = ex2f_(v.x * LOG2E); e.y = ex2f_(v.y * LOG2E);
        e.z = ex2f_(v.z * LOG2E); e.w = ex2f_(v.w * LOG2E);
        reinterpret_cast<float4*>(sm_ef)[i] = e;
    }

    // ---- gold path score (block-parallel over t) ----
    const int* lab = labels + (size_t)b * SS;
    float sc = 0.f;
    for (int t = tid; t < SS; t += 256) {
        int lt = lab[t];
        if (t == 0) {
            sc += __ldg(&start_tr[lt]) + frow[lt];
        } else if (t < len) {
            sc += __ldg(&trans[lab[t - 1] * LL + lt]) + frow[t * LL + lt];
        }
        if (t == len - 1) sc += __ldg(&end_tr[lt]);
    }
#pragma unroll
    for (int o = 16; o > 0; o >>= 1) sc += __shfl_xor_sync(FULL, sc, o);
    if (lane == 0) sm_red[wid] = sc;
    __syncthreads();
    if (tid == 0) {
        float s = 0.f;
        for (int w = 0; w < 8; w++) s += sm_red[w];
        sm_score = s;
    }

    // ---- per-warp segment matrix product ----
    const int a = (lane < 27) ? (lane / 3) : 8;
    const int g = lane % 3;
    float Ec[LL][3];
#pragma unroll
    for (int i = 0; i < LL; i++)
#pragma unroll
        for (int k = 0; k < 3; k++)
            Ec[i][k] = __expf(__ldg(&trans[i * LL + 3 * g + k]));

    float Mr[3];
#pragma unroll
    for (int k = 0; k < 3; k++) Mr[k] = (3 * g + k == a) ? 1.f : 0.f;
    float Cw = 0.f;

    __syncthreads();  // sm_ef ready

    const int t0 = max(1, wid * 64);
    const int t1 = min(len, (wid + 1) * 64);
    for (int t = t0; t < t1; ++t) {
        float ef0 = sm_ef[t * LL + 3 * g + 0];
        float ef1 = sm_ef[t * LL + 3 * g + 1];
        float ef2 = sm_ef[t * LL + 3 * g + 2];

        float m[LL];
#pragma unroll
        for (int i = 0; i < LL; i++)
            m[i] = __shfl_sync(FULL, Mr[i % 3], a * 3 + i / 3);

        float o0a = m[0] * Ec[0][0], o0b = m[1] * Ec[1][0];
        float o1a = m[0] * Ec[0][1], o1b = m[1] * Ec[1][1];
        float o2a = m[0] * Ec[0][2], o2b = m[1] * Ec[1][2];
#pragma unroll
        for (int i = 2; i < LL; i += 2) {
            o0a = fmaf(m[i], Ec[i][0], o0a);
            o1a = fmaf(m[i], Ec[i][1], o1a);
            o2a = fmaf(m[i], Ec[i][2], o2a);
            if (i + 1 < LL) {
                o0b = fmaf(m[i + 1], Ec[i + 1][0], o0b);
                o1b = fmaf(m[i + 1], Ec[i + 1][1], o1b);
                o2b = fmaf(m[i + 1], Ec[i + 1][2], o2b);
            }
        }
        Mr[0] = (o0a + o0b) * ef0;
        Mr[1] = (o1a + o1b) * ef1;
        Mr[2] = (o2a + o2b) * ef2;

        if ((t & 7) == 7) {
            float u = __shfl_sync(FULL, Mr[0], 0);
            int e = (__float_as_int(u) >> 23) & 255;
            float scale = __int_as_float((254 - e) << 23);
            Mr[0] *= scale; Mr[1] *= scale; Mr[2] *= scale;
            Cw += (float)(e - 127);
        }
    }
    if (lane < 27) {
#pragma unroll
        for (int k = 0; k < 3; k++) sm_M[wid][a * LL + 3 * g + k] = Mr[k];
    }
    if (lane == 0) sm_C[wid] = Cw;
    __syncthreads();

    // ---- warp 0: chain alpha through the 8 segment matrices ----
    if (wid == 0) {
        float al = (lane < LL) ? sm_ef[lane] * __expf(__ldg(&start_tr[lane])) : 0.f;
        float C = 0.f;
#pragma unroll 1
        for (int s = 0; s < 8; ++s) {
            float m[LL];
#pragma unroll
            for (int i = 0; i < LL; i++) m[i] = __shfl_sync(FULL, al, i);
            const int jj = (lane < LL) ? lane : 0;
            float sum = 0.f;
#pragma unroll
            for (int i = 0; i < LL; i++)
                sum = fmaf(m[i], sm_M[s][i * LL + jj], sum);
            al = (lane < LL) ? sum : 0.f;
            C += sm_C[s];
            float u = __shfl_sync(FULL, al, 0);
            int e = (__float_as_int(u) >> 23) & 255;
            float scale = __int_as_float((254 - e) << 23);
            al *= scale;
            C += (float)(e - 127);
        }
        float ev = (lane < LL) ? al * __expf(__ldg(&end_tr[lane])) : 0.f;
#pragma unroll
        for (int o = 16; o > 0; o >>= 1) ev += __shfl_xor_sync(FULL, ev, o);
        float logden = LN2 * (C + lg2f_(ev));
        if (lane == 0) partials[b] = logden - sm_score;
    }
}

// ---------------------------------------------------------------------------
// Kernel 3: mean over 64 per-batch NLLs
// ---------------------------------------------------------------------------
__global__ void finalize_kernel(const float* __restrict__ p, float* __restrict__ out) {
    int lane = threadIdx.x;  // 32 threads
    float v = p[lane] + p[lane + 32];
#pragma unroll
    for (int o = 16; o > 0; o >>= 1) v += __shfl_xor_sync(0xffffffffu, v, o);
    if (lane == 0) out[0] = v * (1.0f / BB);
}

// ---------------------------------------------------------------------------
extern "C" void kernel_launch(void* const* d_in, const int* in_sizes, int n_in,
                              void* d_out, int out_size) {
    const float* hidden  = (const float*)d_in[0];
    const float* W       = (const float*)d_in[1];
    const float* bias    = (const float*)d_in[2];
    const float* start_t = (const float*)d_in[3];
    const float* end_t   = (const float*)d_in[4];
    const float* trans   = (const float*)d_in[5];
    const int*   labels  = (const int*)d_in[6];
    const unsigned char* mask = (const unsigned char*)d_in[7];
    float* out = (float*)d_out;

    float* feats = nullptr;
    float* part  = nullptr;
    cudaGetSymbolAddress((void**)&feats, g_feats);
    cudaGetSymbolAddress((void**)&part,  g_part);

    static bool attr_set = false;
    if (!attr_set) {
        cudaFuncSetAttribute(gemm_kernel,
                             cudaFuncAttributeMaxDynamicSharedMemorySize,
                             GEMM_SMEM_BYTES);
        attr_set = true;
    }

    gemm_kernel<<<256, 256, GEMM_SMEM_BYTES>>>(hidden, W, bias, feats);
    crf_kernel<<<BB, 256>>>(feats, start_t, end_t, trans, labels, mask, part);
    finalize_kernel<<<1, 32>>>(part, out);
}

// round 10
// speedup vs baseline: 1.3254x; 1.0521x over previous
#include <cuda_runtime.h>
#include <cuda_bf16.h>
#include <cstdint>

#define BB 64
#define SS 512
#define HH 768
#define LL 9

#define RB 128                    // rows per block (gemm)
#define KC 32                     // k per chunk
#define NCHUNK (HH / KC)          // 24
#define NSTAGE 3                  // per-warp pipeline depth
#define WSTG_U32 (16 * 36)        // 576 u32: one warp-stage (16 rows x 36)
#define AW_U32 (NSTAGE * WSTG_U32)        // per-warp A region
#define A_U32 (8 * AW_U32)                // 13824
#define B0_U32 (96 * 64)          // 6144: ntile0 frag table
#define B1_U32 (96 * 8)           // 768:  ntile1 compact (only n=8 real)
#define SMEM_U32 (A_U32 + B0_U32 + B1_U32)
#define GEMM_SMEM_BYTES (SMEM_U32 * 4)    // 82944

__device__ float g_feats[(size_t)BB * SS * LL];
__device__ float g_part[BB];

__device__ __forceinline__ float ex2f_(float x) {
    float y; asm("ex2.approx.ftz.f32 %0, %1;" : "=f"(y) : "f"(x)); return y;
}
__device__ __forceinline__ float lg2f_(float x) {
    float y; asm("lg2.approx.f32 %0, %1;" : "=f"(y) : "f"(x)); return y;
}
__device__ __forceinline__ uint32_t f2tf32_(float v) {
    uint32_t t; asm("cvt.rna.tf32.f32 %0, %1;" : "=r"(t) : "f"(v)); return t;
}
__device__ __forceinline__ void cpasync16_(uint32_t dst, const void* src) {
    asm volatile("cp.async.cg.shared.global [%0], [%1], 16;"
                 :: "r"(dst), "l"(src));
}

// ---------------------------------------------------------------------------
// Kernel 1 (tensor): feats[m][l] = hidden[m][:].W[l][:] + b[l]
// tf32 mma.sync.m16n8k8; A raw fp32 bits (tf32 truncation, within tol).
// BARRIER-FREE mainloop: warp w computes rows w*16..w*16+15 and its A frags
// come only from those rows -> each warp stages its own A slice via a
// private 3-stage cp.async pipeline (wait_group + syncwarp only; no
// __syncthreads after the B-table build). Warps free-run, so cp.async
// latency is hidden by cross-warp overlap instead of block-burst barriers.
// ---------------------------------------------------------------------------
__global__ __launch_bounds__(256)
void gemm_kernel(const float* __restrict__ hidden,
                 const float* __restrict__ W,
                 const float* __restrict__ bias,
                 float* __restrict__ feats) {
    extern __shared__ uint32_t dynsm[];
    uint32_t* Bfr0 = dynsm + A_U32;              // [96][64]
    uint32_t* Bfr1 = Bfr0 + B0_U32;              // [96][8]
    const uint32_t sbase =
        static_cast<uint32_t>(__cvta_generic_to_shared(dynsm));

    const int tid  = threadIdx.x;
    const int warp = tid >> 5;
    const int lane = tid & 31;
    const int g = lane >> 2;           // 0..7
    const int c = lane & 3;            // 0..3

    // ---- build B fragment tables (once per block) ----
    for (int i = tid; i < B0_U32; i += 256) {
        int half = i & 1;
        int ln   = (i >> 1) & 31;
        int s    = i >> 6;
        int n = ln >> 2;
        int k = s * 8 + (ln & 3) + half * 4;
        Bfr0[i] = f2tf32_(__ldg(&W[n * HH + k]));
    }
    for (int i = tid; i < B1_U32; i += 256) {
        int half = i & 1;
        int ln   = (i >> 1) & 3;
        int s    = i >> 3;
        int k = s * 8 + ln + half * 4;
        Bfr1[i] = f2tf32_(__ldg(&W[8 * HH + k]));
    }

    const int rowbase = blockIdx.x * RB + warp * 16;
    const uint32_t wbase_u32 = (uint32_t)(warp * AW_U32);
    const uint32_t* Aw = dynsm + warp * AW_U32;

    // per-warp staging: 16 rows x 32 k -> stage st. 4 cp.async.16B per lane.
    auto stage = [&](int st, int kc) {
#pragma unroll
        for (int j = 0; j < 4; ++j) {
            int idx = lane + 32 * j;            // 0..127
            int r = idx >> 3, seg = idx & 7;
            uint32_t dst = sbase +
                (wbase_u32 + (uint32_t)(st * WSTG_U32 + r * 36 + seg * 4)) * 4u;
            const float* src = hidden + (size_t)(rowbase + r) * HH
                               + kc * KC + seg * 4;
            cpasync16_(dst, src);
        }
        asm volatile("cp.async.commit_group;");
    };

    float acc[2][4];
#pragma unroll
    for (int nt = 0; nt < 2; ++nt)
#pragma unroll
        for (int j = 0; j < 4; ++j) acc[nt][j] = 0.f;

    // prologue: 3 stages in flight
    stage(0, 0);
    stage(1, 1);
    stage(2, 2);

    __syncthreads();   // B tables ready for all warps

    int st = 0;
#pragma unroll 1
    for (int kc = 0; kc < NCHUNK; ++kc) {
        // wait for chunk kc's group (exact tail handling)
        if (kc <= NCHUNK - 3)
            asm volatile("cp.async.wait_group 2;");
        else if (kc == NCHUNK - 2)
            asm volatile("cp.async.wait_group 1;");
        else
            asm volatile("cp.async.wait_group 0;");
        __syncwarp();   // lanes' copies mutually visible

        const uint32_t* As = Aw + st * WSTG_U32;
#pragma unroll
        for (int s = 0; s < 4; ++s) {
            const uint32_t* a0p = As + g * 36 + s * 8 + c;
            uint32_t a0 = a0p[0];
            uint32_t a2 = a0p[4];
            uint32_t a1 = a0p[8 * 36];
            uint32_t a3 = a0p[8 * 36 + 4];
            int sg = kc * 4 + s;

            uint2 b0 = *reinterpret_cast<const uint2*>(Bfr0 + sg * 64 + lane * 2);
            asm volatile(
                "mma.sync.aligned.m16n8k8.row.col.f32.tf32.tf32.f32 "
                "{%0,%1,%2,%3}, {%4,%5,%6,%7}, {%8,%9}, {%0,%1,%2,%3};"
                : "+f"(acc[0][0]), "+f"(acc[0][1]),
                  "+f"(acc[0][2]), "+f"(acc[0][3])
                : "r"(a0), "r"(a1), "r"(a2), "r"(a3),
                  "r"(b0.x), "r"(b0.y));

            uint2 b1 = make_uint2(0u, 0u);
            if (lane < 4)
                b1 = *reinterpret_cast<const uint2*>(Bfr1 + sg * 8 + lane * 2);
            asm volatile(
                "mma.sync.aligned.m16n8k8.row.col.f32.tf32.tf32.f32 "
                "{%0,%1,%2,%3}, {%4,%5,%6,%7}, {%8,%9}, {%0,%1,%2,%3};"
                : "+f"(acc[1][0]), "+f"(acc[1][1]),
                  "+f"(acc[1][2]), "+f"(acc[1][3])
                : "r"(a0), "r"(a1), "r"(a2), "r"(a3),
                  "r"(b1.x), "r"(b1.y));
        }
        __syncwarp();   // all lanes done reading this stage
        if (kc + NSTAGE < NCHUNK) stage(st, kc + NSTAGE);
        if (++st == NSTAGE) st = 0;
    }

    // ---- epilogue: D frag (rows g/g+8, cols 2c,2c+1 per ntile) ----
    const int row0 = rowbase + g;
    const int row1 = row0 + 8;
#pragma unroll
    for (int nt = 0; nt < 2; ++nt) {
        int col0 = nt * 8 + 2 * c;
        int col1 = col0 + 1;
        if (col0 < LL) {
            float b0 = __ldg(&bias[col0]);
            feats[(size_t)row0 * LL + col0] = acc[nt][0] + b0;
            feats[(size_t)row1 * LL + col0] = acc[nt][2] + b0;
        }
        if (col1 < LL) {
            float b1 = __ldg(&bias[col1]);
            feats[(size_t)row0 * LL + col1] = acc[nt][1] + b1;
            feats[(size_t)row1 * LL + col1] = acc[nt][3] + b1;
        }
    }
}

// ---------------------------------------------------------------------------
// Kernel 2: one block (256 thr, 8 warps) per batch.  (unchanged, proven)
// Blocked parallel CRF scan: warp s computes the 9x9 linear-domain transfer
// matrix product over its 64-step segment; warp 0 chains alpha through the
// 8 matrices. Exact power-of-2 rescale every 8 steps.
// ---------------------------------------------------------------------------
__global__ __launch_bounds__(256, 1)
void crf_kernel(const float* __restrict__ feats,
                const float* __restrict__ start_tr,
                const float* __restrict__ end_tr,
                const float* __restrict__ trans,
                const int* __restrict__ labels,
                const unsigned char* __restrict__ mask8,
                float* __restrict__ partials) {
    __shared__ float sm_ef[SS * LL];
    __shared__ float sm_M[8][81];
    __shared__ float sm_C[8];
    __shared__ float sm_red[8];
    __shared__ float sm_score;
    __shared__ int   sm_len;

    const int b = blockIdx.x;
    const int tid = threadIdx.x;
    const int wid = tid >> 5;
    const int lane = tid & 31;
    const unsigned FULL = 0xffffffffu;
    const float LOG2E = 1.4426950408889634f;
    const float LN2   = 0.6931471805599453f;

    // ---- sequence length (mask monotone: mask[t] = t < len) ----
    const unsigned char* mrow = mask8 + (size_t)b * SS;
    int cnt = 0;
    for (int t = tid; t < SS; t += 256) cnt += (int)mrow[t];
    cnt = __reduce_add_sync(FULL, cnt);
    if (lane == 0) sm_red[wid] = (float)cnt;
    __syncthreads();
    if (tid == 0) {
        int l = 0;
        for (int w = 0; w < 8; w++) l += (int)sm_red[w];
        sm_len = l;
    }
    __syncthreads();
    int len = sm_len;
    if (len < SS / 2) {   // fallback: mask stored as int32 (lens >= 256 if u8)
        const int* mi = reinterpret_cast<const int*>(mask8) + (size_t)b * SS;
        cnt = 0;
        for (int t = tid; t < SS; t += 256) cnt += (mi[t] != 0);
        cnt = __reduce_add_sync(FULL, cnt);
        if (lane == 0) sm_red[wid] = (float)cnt;
        __syncthreads();
        if (tid == 0) {
            int l = 0;
            for (int w = 0; w < 8; w++) l += (int)sm_red[w];
            sm_len = l;
        }
        __syncthreads();
        len = sm_len;
    }
    __syncthreads();

    // ---- ef table: sm_ef[t*9+j] = exp(feats[b][t][j]) (vectorized) ----
    const float* frow = feats + (size_t)b * SS * LL;
    for (int i = tid; i < (SS * LL) / 4; i += 256) {
        float4 v = reinterpret_cast<const float4*>(frow)[i];
        float4 e;
        e.x = ex2f_(v.x * LOG2E); e.y = ex2f_(v.y * LOG2E);
        e.z = ex2f_(v.z * LOG2E); e.w = ex2f_(v.w * LOG2E);
        reinterpret_cast<float4*>(sm_ef)[i] = e;
    }

    // ---- gold path score (block-parallel over t) ----
    const int* lab = labels + (size_t)b * SS;
    float sc = 0.f;
    for (int t = tid; t < SS; t += 256) {
        int lt = lab[t];
        if (t == 0) {
            sc += __ldg(&start_tr[lt]) + frow[lt];
        } else if (t < len) {
            sc += __ldg(&trans[lab[t - 1] * LL + lt]) + frow[t * LL + lt];
        }
        if (t == len - 1) sc += __ldg(&end_tr[lt]);
    }
#pragma unroll
    for (int o = 16; o > 0; o >>= 1) sc += __shfl_xor_sync(FULL, sc, o);
    if (lane == 0) sm_red[wid] = sc;
    __syncthreads();
    if (tid == 0) {
        float s = 0.f;
        for (int w = 0; w < 8; w++) s += sm_red[w];
        sm_score = s;
    }

    // ---- per-warp segment matrix product ----
    const int a = (lane < 27) ? (lane / 3) : 8;
    const int g = lane % 3;
    float Ec[LL][3];
#pragma unroll
    for (int i = 0; i < LL; i++)
#pragma unroll
        for (int k = 0; k < 3; k++)
            Ec[i][k] = __expf(__ldg(&trans[i * LL + 3 * g + k]));

    float Mr[3];
#pragma unroll
    for (int k = 0; k < 3; k++) Mr[k] = (3 * g + k == a) ? 1.f : 0.f;
    float Cw = 0.f;

    __syncthreads();  // sm_ef ready

    const int t0 = max(1, wid * 64);
    const int t1 = min(len, (wid + 1) * 64);
    for (int t = t0; t < t1; ++t) {
        float ef0 = sm_ef[t * LL + 3 * g + 0];
        float ef1 = sm_ef[t * LL + 3 * g + 1];
        float ef2 = sm_ef[t * LL + 3 * g + 2];

        float m[LL];
#pragma unroll
        for (int i = 0; i < LL; i++)
            m[i] = __shfl_sync(FULL, Mr[i % 3], a * 3 + i / 3);

        float o0a = m[0] * Ec[0][0], o0b = m[1] * Ec[1][0];
        float o1a = m[0] * Ec[0][1], o1b = m[1] * Ec[1][1];
        float o2a = m[0] * Ec[0][2], o2b = m[1] * Ec[1][2];
#pragma unroll
        for (int i = 2; i < LL; i += 2) {
            o0a = fmaf(m[i], Ec[i][0], o0a);
            o1a = fmaf(m[i], Ec[i][1], o1a);
            o2a = fmaf(m[i], Ec[i][2], o2a);
            if (i + 1 < LL) {
                o0b = fmaf(m[i + 1], Ec[i + 1][0], o0b);
                o1b = fmaf(m[i + 1], Ec[i + 1][1], o1b);
                o2b = fmaf(m[i + 1], Ec[i + 1][2], o2b);
            }
        }
        Mr[0] = (o0a + o0b) * ef0;
        Mr[1] = (o1a + o1b) * ef1;
        Mr[2] = (o2a + o2b) * ef2;

        if ((t & 7) == 7) {
            float u = __shfl_sync(FULL, Mr[0], 0);
            int e = (__float_as_int(u) >> 23) & 255;
            float scale = __int_as_float((254 - e) << 23);
            Mr[0] *= scale; Mr[1] *= scale; Mr[2] *= scale;
            Cw += (float)(e - 127);
        }
    }
    if (lane < 27) {
#pragma unroll
        for (int k = 0; k < 3; k++) sm_M[wid][a * LL + 3 * g + k] = Mr[k];
    }
    if (lane == 0) sm_C[wid] = Cw;
    __syncthreads();

    // ---- warp 0: chain alpha through the 8 segment matrices ----
    if (wid == 0) {
        float al = (lane < LL) ? sm_ef[lane] * __expf(__ldg(&start_tr[lane])) : 0.f;
        float C = 0.f;
#pragma unroll 1
        for (int s = 0; s < 8; ++s) {
            float m[LL];
#pragma unroll
            for (int i = 0; i < LL; i++) m[i] = __shfl_sync(FULL, al, i);
            const int jj = (lane < LL) ? lane : 0;
            float sum = 0.f;
#pragma unroll
            for (int i = 0; i < LL; i++)
                sum = fmaf(m[i], sm_M[s][i * LL + jj], sum);
            al = (lane < LL) ? sum : 0.f;
            C += sm_C[s];
            float u = __shfl_sync(FULL, al, 0);
            int e = (__float_as_int(u) >> 23) & 255;
            float scale = __int_as_float((254 - e) << 23);
            al *= scale;
            C += (float)(e - 127);
        }
        float ev = (lane < LL) ? al * __expf(__ldg(&end_tr[lane])) : 0.f;
#pragma unroll
        for (int o = 16; o > 0; o >>= 1) ev += __shfl_xor_sync(FULL, ev, o);
        float logden = LN2 * (C + lg2f_(ev));
        if (lane == 0) partials[b] = logden - sm_score;
    }
}

// ---------------------------------------------------------------------------
// Kernel 3: mean over 64 per-batch NLLs
// ---------------------------------------------------------------------------
__global__ void finalize_kernel(const float* __restrict__ p, float* __restrict__ out) {
    int lane = threadIdx.x;  // 32 threads
    float v = p[lane] + p[lane + 32];
#pragma unroll
    for (int o = 16; o > 0; o >>= 1) v += __shfl_xor_sync(0xffffffffu, v, o);
    if (lane == 0) out[0] = v * (1.0f / BB);
}

// ---------------------------------------------------------------------------
extern "C" void kernel_launch(void* const* d_in, const int* in_sizes, int n_in,
                              void* d_out, int out_size) {
    const float* hidden  = (const float*)d_in[0];
    const float* W       = (const float*)d_in[1];
    const float* bias    = (const float*)d_in[2];
    const float* start_t = (const float*)d_in[3];
    const float* end_t   = (const float*)d_in[4];
    const float* trans   = (const float*)d_in[5];
    const int*   labels  = (const int*)d_in[6];
    const unsigned char* mask = (const unsigned char*)d_in[7];
    float* out = (float*)d_out;

    float* feats = nullptr;
    float* part  = nullptr;
    cudaGetSymbolAddress((void**)&feats, g_feats);
    cudaGetSymbolAddress((void**)&part,  g_part);

    static bool attr_set = false;
    if (!attr_set) {
        cudaFuncSetAttribute(gemm_kernel,
                             cudaFuncAttributeMaxDynamicSharedMemorySize,
                             GEMM_SMEM_BYTES);
        attr_set = true;
    }

    gemm_kernel<<<256, 256, GEMM_SMEM_BYTES>>>(hidden, W, bias, feats);
    crf_kernel<<<BB, 256>>>(feats, start_t, end_t, trans, labels, mask, part);
    finalize_kernel<<<1, 32>>>(part, out);
}